// round 4
// baseline (speedup 1.0000x reference)
#include <cuda_runtime.h>

typedef unsigned long long ull;

#define NEXPERTS 64
#define S_MAX    8192

// static scratch (no allocations allowed)
__device__ int   g_idx[S_MAX];
__device__ float g_gate[S_MAX];
__device__ float g_me_partial[(S_MAX / 64) * NEXPERTS];  // per-gemm-block gate sums
__device__ int   g_cnt[(S_MAX / 512) * NEXPERTS];        // per-chunk expert counts
__device__ int   g_base[(S_MAX / 512) * NEXPERTS];       // exclusive prefix per chunk
__device__ int   g_rank[S_MAX];                          // rank within chunk
__device__ float g_laux;

__device__ __forceinline__ ull pack2(float lo, float hi) {
    ull r; asm("mov.b64 %0, {%1, %2};" : "=l"(r) : "f"(lo), "f"(hi)); return r;
}
__device__ __forceinline__ void ffma2(ull& d, ull a, ull b) {
    asm("fma.rn.f32x2 %0, %1, %2, %0;" : "+l"(d) : "l"(a), "l"(b));
}
__device__ __forceinline__ float2 unpack2(ull v) {
    float2 r; asm("mov.b64 {%0, %1}, %2;" : "=f"(r.x), "=f"(r.y) : "l"(v)); return r;
}

// ---------------------------------------------------------------------------
// Kernel 1: logits = x @ wg^T for a 64-token tile (full K), then per-token
// softmax/argmax/gate IN the epilogue (logits never leave the SM).
// 256 threads, micro 4 tok x 4 exp, FFMA2-packed accumulators.
// ---------------------------------------------------------------------------
__global__ __launch_bounds__(256) void gemm_softmax(const float* __restrict__ x,
                                                    const float* __restrict__ wg,
                                                    int D, int S) {
    __shared__ float sm[64 * 68];          // As[32][68] + Bs[32][68], reused as Ls[64][68]
    __shared__ float sm_m[64], sm_inv[64], red[4][64];
    float (*As)[68] = (float(*)[68])sm;
    float (*Bs)[68] = (float(*)[68])(sm + 32 * 68);
    float (*Ls)[68] = (float(*)[68])sm;

    const int tid = threadIdx.x;
    const int ty  = tid >> 4;      // 0..15 -> tokens ty*4 .. ty*4+3
    const int tx  = tid & 15;      // 0..15 -> experts tx*4 .. tx*4+3
    const int s0  = blockIdx.x * 64;

    ull acc[2][4];
#pragma unroll
    for (int i = 0; i < 2; ++i)
#pragma unroll
        for (int j = 0; j < 4; ++j) acc[i][j] = 0ull;

    for (int kt = 0; kt < D; kt += 32) {
#pragma unroll
        for (int r = 0; r < 2; ++r) {
            int i   = tid + r * 256;       // 0..511 float4 groups
            int row = i >> 3;              // 0..63
            int k4  = (i & 7) << 2;        // 0,4,...,28
            float4 av = *(const float4*)(x  + (size_t)(s0 + row) * D + kt + k4);
            As[k4 + 0][row] = av.x; As[k4 + 1][row] = av.y;
            As[k4 + 2][row] = av.z; As[k4 + 3][row] = av.w;
            float4 bv = *(const float4*)(wg + (size_t)row * D + kt + k4);
            Bs[k4 + 0][row] = bv.x; Bs[k4 + 1][row] = bv.y;
            Bs[k4 + 2][row] = bv.z; Bs[k4 + 3][row] = bv.w;
        }
        __syncthreads();
#pragma unroll
        for (int k = 0; k < 32; ++k) {
            ulonglong2 A0 = *(const ulonglong2*)&As[k][ty * 4];
            ull a0 = A0.x, a1 = A0.y;                       // 4 tokens (2 pairs)
            float4 bv = *(const float4*)&Bs[k][tx * 4];
            ull b0 = pack2(bv.x, bv.x), b1 = pack2(bv.y, bv.y);
            ull b2 = pack2(bv.z, bv.z), b3 = pack2(bv.w, bv.w);
            ffma2(acc[0][0], a0, b0); ffma2(acc[0][1], a0, b1);
            ffma2(acc[0][2], a0, b2); ffma2(acc[0][3], a0, b3);
            ffma2(acc[1][0], a1, b0); ffma2(acc[1][1], a1, b1);
            ffma2(acc[1][2], a1, b2); ffma2(acc[1][3], a1, b3);
        }
        __syncthreads();
    }

    // dump logit tile into smem (As/Bs region is dead now)
#pragma unroll
    for (int i = 0; i < 2; ++i) {
        float2 c0 = unpack2(acc[i][0]);
        float2 c1 = unpack2(acc[i][1]);
        float2 c2 = unpack2(acc[i][2]);
        float2 c3 = unpack2(acc[i][3]);
        int t0 = ty * 4 + 2 * i;
        *(float4*)&Ls[t0][tx * 4]     = make_float4(c0.x, c1.x, c2.x, c3.x);
        *(float4*)&Ls[t0 + 1][tx * 4] = make_float4(c0.y, c1.y, c2.y, c3.y);
    }
    __syncthreads();

    // per-token softmax + argmax (first max wins = jnp.argmax)
    if (tid < 64) {
        float m = -1e30f; int ix = 0;
#pragma unroll 8
        for (int e = 0; e < 64; ++e) {
            float v = Ls[tid][e];
            if (v > m) { m = v; ix = e; }
        }
        float ssum = 0.f;
#pragma unroll 8
        for (int e = 0; e < 64; ++e) ssum += expf(Ls[tid][e] - m);
        float inv = 1.0f / ssum;
        g_idx[s0 + tid]  = ix;
        g_gate[s0 + tid] = inv;
        sm_m[tid] = m; sm_inv[tid] = inv;
    }
    __syncthreads();

    // per-block me partials: me_e += sum_t softmax(l)[t][e]
    {
        const int e = tid & 63, q = tid >> 6;
        float mp = 0.f;
#pragma unroll
        for (int t = q * 16; t < q * 16 + 16; ++t)
            mp += expf(Ls[t][e] - sm_m[t]) * sm_inv[t];
        red[q][e] = mp;
    }
    __syncthreads();
    if (tid < 64)
        g_me_partial[(size_t)blockIdx.x * 64 + tid] =
            red[0][tid] + red[1][tid] + red[2][tid] + red[3][tid];
}

// ---------------------------------------------------------------------------
// Kernel 2: per-512-token chunk: warp-ballot ranks + per-chunk expert counts.
// rank-in-chunk respects token order (warp order x lane order).
// ---------------------------------------------------------------------------
__global__ __launch_bounds__(512) void hist_rank() {
    __shared__ int hist[16][64];
    const int tid  = threadIdx.x;
    const int lane = tid & 31;
    const int warp = tid >> 5;
    const int s = blockIdx.x * 512 + tid;

    hist[tid >> 6][tid & 63] = 0;
    ((int*)hist)[512 + tid] = 0;
    __syncthreads();

    const int e = g_idx[s];
    unsigned mask = __match_any_sync(0xffffffffu, e);
    int inrank = __popc(mask & ((1u << lane) - 1));
    int cnt    = __popc(mask);
    if (inrank == 0) hist[warp][e] = cnt;
    __syncthreads();

    if (tid < 64) {            // exclusive prefix over the 16 warps, per expert
        int run = 0;
#pragma unroll
        for (int w = 0; w < 16; ++w) {
            int t = hist[w][tid]; hist[w][tid] = run; run += t;
        }
        g_cnt[blockIdx.x * 64 + tid] = run;
    }
    __syncthreads();
    g_rank[s] = hist[warp][e] + inrank;
}

// ---------------------------------------------------------------------------
// Kernel 3 (tiny, 1 block): chunk prefix per expert + l_aux.
// ---------------------------------------------------------------------------
__global__ __launch_bounds__(1024) void prefix_laux(int S, int nblk, int nchunks) {
    __shared__ float red[16][64];
    __shared__ float prod[64];
    const int tid = threadIdx.x;
    const int e = tid & 63, p = tid >> 6;   // p: 0..15

    float mp = 0.f;
    for (int b = p; b < nblk; b += 16) mp += g_me_partial[(size_t)b * 64 + e];
    red[p][e] = mp;

    if (tid < 64) {
        int run = 0;
        for (int c = 0; c < nchunks; ++c) {
            int t = g_cnt[c * 64 + tid];
            g_base[c * 64 + tid] = run;
            run += t;
        }
        prod[tid] = (float)run / (float)S;   // ce (pre-drop counts)
    }
    __syncthreads();
    if (tid < 64) {
        float me = 0.f;
#pragma unroll
        for (int q = 0; q < 16; ++q) me += red[q][tid];
        prod[tid] *= me / (float)S;
    }
    __syncthreads();
    if (tid == 0) {
        float sum = 0.f;
        for (int ee = 0; ee < 64; ++ee) sum += prod[ee];
        g_laux = sum * (float)NEXPERTS;      // mean(me*ce)*E^2 = sum*E
    }
}

// ---------------------------------------------------------------------------
// Kernel 4: sparse scatter into the (memset-zeroed) output. After the join.
// ---------------------------------------------------------------------------
__global__ void scatter_out(float* __restrict__ out, int S, int C,
                            long long comb_off, long long disp_off, int write_aux) {
    int s = blockIdx.x * blockDim.x + threadIdx.x;
    if (s == 0 && write_aux) out[0] = g_laux;
    if (s < S) {
        int e = g_idx[s];
        int r = g_base[(s >> 9) * 64 + e] + g_rank[s];
        if (r < C) {
            size_t pos = ((size_t)s * NEXPERTS + e) * (size_t)C + r;
            out[(size_t)comb_off + pos] = g_gate[s];
            if (disp_off >= 0)
                out[(size_t)disp_off + pos] = 1.0f;
        }
    }
}

extern "C" void kernel_launch(void* const* d_in, const int* in_sizes, int n_in,
                              void* d_out, int out_size) {
    const float* x  = (const float*)d_in[0];
    const float* wg = (const float*)d_in[1];
    const int D = in_sizes[1] / NEXPERTS;
    const int S = in_sizes[0] / D;
    const int C = (S + NEXPERTS - 1) / NEXPERTS;   // capacity_factor = 1.0
    const size_t SEC = (size_t)S * NEXPERTS * C;
    const size_t osz = (size_t)out_size;

    // output layout: [l_aux(1)][combine(SEC)][dispatch(SEC)] when sizes match
    long long comb = 0, disp = -1; int aux = 0;
    if (osz >= 2 * SEC + 1)      { aux = 1; comb = 1; disp = 1 + (long long)SEC; }
    else if (osz >= 2 * SEC)     { comb = 0; disp = (long long)SEC; }

    // Fork a parallel branch: the 537MB zero-fill (memset node) runs
    // concurrently with the compute chain, which touches only scratch.
    // Joined before the sparse scatter writes into d_out.
    cudaStream_t s1; cudaStreamCreate(&s1);
    cudaEvent_t ef, ej;
    cudaEventCreateWithFlags(&ef, cudaEventDisableTiming);
    cudaEventCreateWithFlags(&ej, cudaEventDisableTiming);

    cudaEventRecord(ef, 0);
    cudaStreamWaitEvent(s1, ef, 0);
    cudaMemsetAsync(d_out, 0, osz * sizeof(float), s1);      // branch B
    cudaEventRecord(ej, s1);

    gemm_softmax<<<S / 64, 256>>>(x, wg, D, S);              // branch A (scratch only)
    hist_rank<<<S / 512, 512>>>();
    prefix_laux<<<1, 1024>>>(S, S / 64, S / 512);

    cudaStreamWaitEvent(0, ej, 0);                           // join
    scatter_out<<<(S + 255) / 256, 256>>>((float*)d_out, S, C, comb, disp, aux);
    // s1/ef/ej intentionally not destroyed: kernel_launch runs only a handful
    // of times (correctness + capture), and destroying capture-referenced
    // objects mid-capture is unsafe.
}

// round 5
// speedup vs baseline: 1.6113x; 1.6113x over previous
#include <cuda_runtime.h>

typedef unsigned long long ull;

#define NEXPERTS 64
#define S_MAX    8192

// static scratch (no allocations allowed)
__device__ int   g_idx[S_MAX];
__device__ float g_gate[S_MAX];
__device__ float g_me_partial[(S_MAX / 64) * NEXPERTS];  // per-gemm-block gate sums
__device__ int   g_cnt[(S_MAX / 512) * NEXPERTS];        // per-chunk expert counts
__device__ int   g_base[(S_MAX / 512) * NEXPERTS];       // exclusive prefix per chunk
__device__ int   g_rank[S_MAX];                          // rank within chunk
__device__ float g_laux;

__device__ __forceinline__ ull pack2(float lo, float hi) {
    ull r; asm("mov.b64 %0, {%1, %2};" : "=l"(r) : "f"(lo), "f"(hi)); return r;
}
__device__ __forceinline__ void ffma2(ull& d, ull a, ull b) {
    asm("fma.rn.f32x2 %0, %1, %2, %0;" : "+l"(d) : "l"(a), "l"(b));
}
__device__ __forceinline__ float2 unpack2(ull v) {
    float2 r; asm("mov.b64 {%0, %1}, %2;" : "=f"(r.x), "=f"(r.y) : "l"(v)); return r;
}

// ---------------------------------------------------------------------------
// Kernel 1: logits = x @ wg^T for a 64-token tile (full K), then per-token
// softmax/argmax/gate IN the epilogue (logits never leave the SM).
// 256 threads, micro 4 tok x 4 exp, FFMA2-packed accumulators.
// ---------------------------------------------------------------------------
__global__ __launch_bounds__(256) void gemm_softmax(const float* __restrict__ x,
                                                    const float* __restrict__ wg,
                                                    int D, int S) {
    __shared__ float sm[64 * 68];          // As[32][68] + Bs[32][68], reused as Ls[64][68]
    __shared__ float sm_m[64], sm_inv[64], red[4][64];
    float (*As)[68] = (float(*)[68])sm;
    float (*Bs)[68] = (float(*)[68])(sm + 32 * 68);
    float (*Ls)[68] = (float(*)[68])sm;

    const int tid = threadIdx.x;
    const int ty  = tid >> 4;      // 0..15 -> tokens ty*4 .. ty*4+3
    const int tx  = tid & 15;      // 0..15 -> experts tx*4 .. tx*4+3
    const int s0  = blockIdx.x * 64;

    ull acc[2][4];
#pragma unroll
    for (int i = 0; i < 2; ++i)
#pragma unroll
        for (int j = 0; j < 4; ++j) acc[i][j] = 0ull;

    for (int kt = 0; kt < D; kt += 32) {
#pragma unroll
        for (int r = 0; r < 2; ++r) {
            int i   = tid + r * 256;       // 0..511 float4 groups
            int row = i >> 3;              // 0..63
            int k4  = (i & 7) << 2;        // 0,4,...,28
            float4 av = *(const float4*)(x  + (size_t)(s0 + row) * D + kt + k4);
            As[k4 + 0][row] = av.x; As[k4 + 1][row] = av.y;
            As[k4 + 2][row] = av.z; As[k4 + 3][row] = av.w;
            float4 bv = *(const float4*)(wg + (size_t)row * D + kt + k4);
            Bs[k4 + 0][row] = bv.x; Bs[k4 + 1][row] = bv.y;
            Bs[k4 + 2][row] = bv.z; Bs[k4 + 3][row] = bv.w;
        }
        __syncthreads();
#pragma unroll
        for (int k = 0; k < 32; ++k) {
            ulonglong2 A0 = *(const ulonglong2*)&As[k][ty * 4];
            ull a0 = A0.x, a1 = A0.y;                       // 4 tokens (2 pairs)
            float4 bv = *(const float4*)&Bs[k][tx * 4];
            ull b0 = pack2(bv.x, bv.x), b1 = pack2(bv.y, bv.y);
            ull b2 = pack2(bv.z, bv.z), b3 = pack2(bv.w, bv.w);
            ffma2(acc[0][0], a0, b0); ffma2(acc[0][1], a0, b1);
            ffma2(acc[0][2], a0, b2); ffma2(acc[0][3], a0, b3);
            ffma2(acc[1][0], a1, b0); ffma2(acc[1][1], a1, b1);
            ffma2(acc[1][2], a1, b2); ffma2(acc[1][3], a1, b3);
        }
        __syncthreads();
    }

    // dump logit tile into smem (As/Bs region is dead now)
#pragma unroll
    for (int i = 0; i < 2; ++i) {
        float2 c0 = unpack2(acc[i][0]);
        float2 c1 = unpack2(acc[i][1]);
        float2 c2 = unpack2(acc[i][2]);
        float2 c3 = unpack2(acc[i][3]);
        int t0 = ty * 4 + 2 * i;
        *(float4*)&Ls[t0][tx * 4]     = make_float4(c0.x, c1.x, c2.x, c3.x);
        *(float4*)&Ls[t0 + 1][tx * 4] = make_float4(c0.y, c1.y, c2.y, c3.y);
    }
    __syncthreads();

    // per-token softmax + argmax (first max wins = jnp.argmax)
    if (tid < 64) {
        float m = -1e30f; int ix = 0;
#pragma unroll 8
        for (int e = 0; e < 64; ++e) {
            float v = Ls[tid][e];
            if (v > m) { m = v; ix = e; }
        }
        float ssum = 0.f;
#pragma unroll 8
        for (int e = 0; e < 64; ++e) ssum += expf(Ls[tid][e] - m);
        float inv = 1.0f / ssum;
        g_idx[s0 + tid]  = ix;
        g_gate[s0 + tid] = inv;
        sm_m[tid] = m; sm_inv[tid] = inv;
    }
    __syncthreads();

    // per-block me partials: me_e += sum_t softmax(l)[t][e]
    {
        const int e = tid & 63, q = tid >> 6;
        float mp = 0.f;
#pragma unroll
        for (int t = q * 16; t < q * 16 + 16; ++t)
            mp += expf(Ls[t][e] - sm_m[t]) * sm_inv[t];
        red[q][e] = mp;
    }
    __syncthreads();
    if (tid < 64)
        g_me_partial[(size_t)blockIdx.x * 64 + tid] =
            red[0][tid] + red[1][tid] + red[2][tid] + red[3][tid];
}

// ---------------------------------------------------------------------------
// Kernel 2: per-512-token chunk: warp-ballot ranks + per-chunk expert counts.
// rank-in-chunk respects token order (warp order x lane order).
// ---------------------------------------------------------------------------
__global__ __launch_bounds__(512) void hist_rank() {
    __shared__ int hist[16][64];
    const int tid  = threadIdx.x;
    const int lane = tid & 31;
    const int warp = tid >> 5;
    const int s = blockIdx.x * 512 + tid;

    hist[tid >> 6][tid & 63] = 0;
    ((int*)hist)[512 + tid] = 0;
    __syncthreads();

    const int e = g_idx[s];
    unsigned mask = __match_any_sync(0xffffffffu, e);
    int inrank = __popc(mask & ((1u << lane) - 1));
    int cnt    = __popc(mask);
    if (inrank == 0) hist[warp][e] = cnt;
    __syncthreads();

    if (tid < 64) {            // exclusive prefix over the 16 warps, per expert
        int run = 0;
#pragma unroll
        for (int w = 0; w < 16; ++w) {
            int t = hist[w][tid]; hist[w][tid] = run; run += t;
        }
        g_cnt[blockIdx.x * 64 + tid] = run;
    }
    __syncthreads();
    g_rank[s] = hist[warp][e] + inrank;
}

// ---------------------------------------------------------------------------
// Kernel 3 (tiny, 1 block): chunk prefix per expert + l_aux.
// ---------------------------------------------------------------------------
__global__ __launch_bounds__(1024) void prefix_laux(int S, int nblk, int nchunks) {
    __shared__ float red[16][64];
    __shared__ float prod[64];
    const int tid = threadIdx.x;
    const int e = tid & 63, p = tid >> 6;   // p: 0..15

    float mp = 0.f;
    for (int b = p; b < nblk; b += 16) mp += g_me_partial[(size_t)b * 64 + e];
    red[p][e] = mp;

    if (tid < 64) {
        int run = 0;
        for (int c = 0; c < nchunks; ++c) {
            int t = g_cnt[c * 64 + tid];
            g_base[c * 64 + tid] = run;
            run += t;
        }
        prod[tid] = (float)run / (float)S;   // ce (pre-drop counts)
    }
    __syncthreads();
    if (tid < 64) {
        float me = 0.f;
#pragma unroll
        for (int q = 0; q < 16; ++q) me += red[q][tid];
        prod[tid] *= me / (float)S;
    }
    __syncthreads();
    if (tid == 0) {
        float sum = 0.f;
        for (int ee = 0; ee < 64; ++ee) sum += prod[ee];
        g_laux = sum * (float)NEXPERTS;      // mean(me*ce)*E^2 = sum*E
    }
}

// ---------------------------------------------------------------------------
// Kernel 4: sparse scatter into the (memset-zeroed) output.
// ---------------------------------------------------------------------------
__global__ void scatter_out(float* __restrict__ out, int S, int C,
                            long long comb_off, long long disp_off, int write_aux) {
    int s = blockIdx.x * blockDim.x + threadIdx.x;
    if (s == 0 && write_aux) out[0] = g_laux;
    if (s < S) {
        int e = g_idx[s];
        int r = g_base[(s >> 9) * 64 + e] + g_rank[s];
        if (r < C) {
            size_t pos = ((size_t)s * NEXPERTS + e) * (size_t)C + r;
            out[(size_t)comb_off + pos] = g_gate[s];
            if (disp_off >= 0)
                out[(size_t)disp_off + pos] = 1.0f;
        }
    }
}

extern "C" void kernel_launch(void* const* d_in, const int* in_sizes, int n_in,
                              void* d_out, int out_size) {
    const float* x  = (const float*)d_in[0];
    const float* wg = (const float*)d_in[1];
    const int D = in_sizes[1] / NEXPERTS;
    const int S = in_sizes[0] / D;
    const int C = (S + NEXPERTS - 1) / NEXPERTS;   // capacity_factor = 1.0
    const size_t SEC = (size_t)S * NEXPERTS * C;
    const size_t osz = (size_t)out_size;

    // output layout: [l_aux(1)][combine(SEC)][dispatch(SEC)] when sizes match
    long long comb = 0, disp = -1; int aux = 0;
    if (osz >= 2 * SEC + 1)      { aux = 1; comb = 1; disp = 1 + (long long)SEC; }
    else if (osz >= 2 * SEC)     { comb = 0; disp = (long long)SEC; }

    // Serial memset on the captured stream — this placement hits the fast
    // (~7 TB/s) SM-side memset path; forked-branch memset nodes fall onto a
    // ~2 TB/s copy-engine queue (round-4 regression).
    cudaMemsetAsync(d_out, 0, osz * sizeof(float), 0);

    gemm_softmax<<<S / 64, 256>>>(x, wg, D, S);
    hist_rank<<<S / 512, 512>>>();
    prefix_laux<<<1, 1024>>>(S, S / 64, S / 512);
    scatter_out<<<(S + 255) / 256, 256>>>((float*)d_out, S, C, comb, disp, aux);
}

// round 6
// speedup vs baseline: 1.6458x; 1.0214x over previous
#include <cuda_runtime.h>

typedef unsigned long long ull;

#define NEXPERTS 64
#define S_MAX    8192

// static scratch (no allocations allowed)
__device__ int   g_idx[S_MAX];
__device__ float g_gate[S_MAX];
__device__ float g_me_partial[(S_MAX / 64) * NEXPERTS];  // per-gemm-block gate sums
__device__ int   g_cnt[(S_MAX / 512) * NEXPERTS];        // per-chunk expert counts
__device__ int   g_base[(S_MAX / 512) * NEXPERTS];       // exclusive prefix per chunk
__device__ int   g_rank[S_MAX];                          // rank within chunk
__device__ float g_laux;

__device__ __forceinline__ ull pack2(float lo, float hi) {
    ull r; asm("mov.b64 %0, {%1, %2};" : "=l"(r) : "f"(lo), "f"(hi)); return r;
}
__device__ __forceinline__ void ffma2(ull& d, ull a, ull b) {
    asm("fma.rn.f32x2 %0, %1, %2, %0;" : "+l"(d) : "l"(a), "l"(b));
}
__device__ __forceinline__ float2 unpack2(ull v) {
    float2 r; asm("mov.b64 {%0, %1}, %2;" : "=f"(r.x), "=f"(r.y) : "l"(v)); return r;
}

// ---------------------------------------------------------------------------
// Zero-fill kernel (forked branch): SM-side streaming stores, overlaps with
// the compute chain. 592 blocks (≈4/SM) leaves room for gemm blocks.
// ---------------------------------------------------------------------------
__global__ __launch_bounds__(256) void zero_fill(float4* __restrict__ o4, size_t n4,
                                                 float* __restrict__ o, size_t osz) {
    const float4 z = make_float4(0.f, 0.f, 0.f, 0.f);
    const size_t stride = (size_t)gridDim.x * 256;
    size_t i = (size_t)blockIdx.x * 256 + threadIdx.x;
    for (; i + 3 * stride < n4; i += 4 * stride) {
        o4[i]              = z;
        o4[i + stride]     = z;
        o4[i + 2 * stride] = z;
        o4[i + 3 * stride] = z;
    }
    for (; i < n4; i += stride) o4[i] = z;
    if (blockIdx.x == 0 && threadIdx.x == 0)
        for (size_t t = n4 * 4; t < osz; ++t) o[t] = 0.f;
}

// ---------------------------------------------------------------------------
// Kernel 1: logits = x @ wg^T for a 64-token tile (full K) + fused per-token
// softmax/argmax epilogue. 128 threads, micro 8 tok x 4 exp (better
// FFMA2:LDS ratio), register prefetch of next k-tile hides LDG latency.
// ---------------------------------------------------------------------------
__global__ __launch_bounds__(128) void gemm_softmax(const float* __restrict__ x,
                                                    const float* __restrict__ wg,
                                                    int D, int S) {
    __shared__ float sm[64 * 68];          // As[32][68] + Bs[32][68] -> Ls[64][68]
    __shared__ float sm_m[64], sm_inv[64], red2[2][64];
    float (*As)[68] = (float(*)[68])sm;
    float (*Bs)[68] = (float(*)[68])(sm + 32 * 68);
    float (*Ls)[68] = (float(*)[68])sm;

    const int tid = threadIdx.x;
    const int ty  = tid >> 4;      // 0..7  -> tokens ty*8 .. ty*8+7
    const int tx  = tid & 15;      // 0..15 -> experts tx*4 .. tx*4+3
    const int s0  = blockIdx.x * 64;

    // loader geometry: i = tid + r*128 (r=0..3) -> row=i>>3 (0..63), k4=(i&7)*4
    int rowr[4], k4r[4];
    const float *xp[4], *wp[4];
#pragma unroll
    for (int r = 0; r < 4; ++r) {
        int i = tid + r * 128;
        rowr[r] = i >> 3; k4r[r] = (i & 7) << 2;
        xp[r] = x  + (size_t)(s0 + rowr[r]) * D + k4r[r];
        wp[r] = wg + (size_t)rowr[r] * D + k4r[r];
    }

    ull acc[4][4];
#pragma unroll
    for (int i = 0; i < 4; ++i)
#pragma unroll
        for (int j = 0; j < 4; ++j) acc[i][j] = 0ull;

    float4 pa[4], pb[4];
#pragma unroll
    for (int r = 0; r < 4; ++r) { pa[r] = *(const float4*)(xp[r]); pb[r] = *(const float4*)(wp[r]); }

    for (int kt = 0; kt < D; kt += 32) {
#pragma unroll
        for (int r = 0; r < 4; ++r) {
            int row = rowr[r], k4 = k4r[r];
            As[k4 + 0][row] = pa[r].x; As[k4 + 1][row] = pa[r].y;
            As[k4 + 2][row] = pa[r].z; As[k4 + 3][row] = pa[r].w;
            Bs[k4 + 0][row] = pb[r].x; Bs[k4 + 1][row] = pb[r].y;
            Bs[k4 + 2][row] = pb[r].z; Bs[k4 + 3][row] = pb[r].w;
        }
        __syncthreads();
        if (kt + 32 < D) {
#pragma unroll
            for (int r = 0; r < 4; ++r) {
                pa[r] = *(const float4*)(xp[r] + kt + 32);
                pb[r] = *(const float4*)(wp[r] + kt + 32);
            }
        }
#pragma unroll
        for (int k = 0; k < 32; ++k) {
            ulonglong2 A0 = *(const ulonglong2*)&As[k][ty * 8];
            ulonglong2 A1 = *(const ulonglong2*)&As[k][ty * 8 + 4];
            ull a0 = A0.x, a1 = A0.y, a2 = A1.x, a3 = A1.y;   // 8 tokens (4 pairs)
            float4 bv = *(const float4*)&Bs[k][tx * 4];
            ull b0 = pack2(bv.x, bv.x), b1 = pack2(bv.y, bv.y);
            ull b2 = pack2(bv.z, bv.z), b3 = pack2(bv.w, bv.w);
            ffma2(acc[0][0], a0, b0); ffma2(acc[0][1], a0, b1);
            ffma2(acc[0][2], a0, b2); ffma2(acc[0][3], a0, b3);
            ffma2(acc[1][0], a1, b0); ffma2(acc[1][1], a1, b1);
            ffma2(acc[1][2], a1, b2); ffma2(acc[1][3], a1, b3);
            ffma2(acc[2][0], a2, b0); ffma2(acc[2][1], a2, b1);
            ffma2(acc[2][2], a2, b2); ffma2(acc[2][3], a2, b3);
            ffma2(acc[3][0], a3, b0); ffma2(acc[3][1], a3, b1);
            ffma2(acc[3][2], a3, b2); ffma2(acc[3][3], a3, b3);
        }
        __syncthreads();
    }

    // dump logit tile into smem (As/Bs region is dead now)
#pragma unroll
    for (int i = 0; i < 4; ++i) {
        float2 c0 = unpack2(acc[i][0]);
        float2 c1 = unpack2(acc[i][1]);
        float2 c2 = unpack2(acc[i][2]);
        float2 c3 = unpack2(acc[i][3]);
        int t0 = ty * 8 + 2 * i;
        *(float4*)&Ls[t0][tx * 4]     = make_float4(c0.x, c1.x, c2.x, c3.x);
        *(float4*)&Ls[t0 + 1][tx * 4] = make_float4(c0.y, c1.y, c2.y, c3.y);
    }
    __syncthreads();

    // per-token softmax + argmax (first max wins = jnp.argmax)
    if (tid < 64) {
        float m = -1e30f; int ix = 0;
#pragma unroll 8
        for (int e = 0; e < 64; ++e) {
            float v = Ls[tid][e];
            if (v > m) { m = v; ix = e; }
        }
        float ssum = 0.f;
#pragma unroll 8
        for (int e = 0; e < 64; ++e) ssum += expf(Ls[tid][e] - m);
        float inv = 1.0f / ssum;
        g_idx[s0 + tid]  = ix;
        g_gate[s0 + tid] = inv;
        sm_m[tid] = m; sm_inv[tid] = inv;
    }
    __syncthreads();

    // per-block me partials: me_e += sum_t softmax(l)[t][e]
    {
        const int e = tid & 63, q = tid >> 6;     // q: 0..1, 32 tokens each
        float mp = 0.f;
#pragma unroll
        for (int t = q * 32; t < q * 32 + 32; ++t)
            mp += expf(Ls[t][e] - sm_m[t]) * sm_inv[t];
        red2[q][e] = mp;
    }
    __syncthreads();
    if (tid < 64)
        g_me_partial[(size_t)blockIdx.x * 64 + tid] = red2[0][tid] + red2[1][tid];
}

// ---------------------------------------------------------------------------
// Kernel 2: per-512-token chunk: warp-ballot ranks + per-chunk expert counts.
// ---------------------------------------------------------------------------
__global__ __launch_bounds__(512) void hist_rank() {
    __shared__ int hist[16][64];
    const int tid  = threadIdx.x;
    const int lane = tid & 31;
    const int warp = tid >> 5;
    const int s = blockIdx.x * 512 + tid;

    hist[tid >> 6][tid & 63] = 0;
    ((int*)hist)[512 + tid] = 0;
    __syncthreads();

    const int e = g_idx[s];
    unsigned mask = __match_any_sync(0xffffffffu, e);
    int inrank = __popc(mask & ((1u << lane) - 1));
    int cnt    = __popc(mask);
    if (inrank == 0) hist[warp][e] = cnt;
    __syncthreads();

    if (tid < 64) {            // exclusive prefix over the 16 warps, per expert
        int run = 0;
#pragma unroll
        for (int w = 0; w < 16; ++w) {
            int t = hist[w][tid]; hist[w][tid] = run; run += t;
        }
        g_cnt[blockIdx.x * 64 + tid] = run;
    }
    __syncthreads();
    g_rank[s] = hist[warp][e] + inrank;
}

// ---------------------------------------------------------------------------
// Kernel 3 (tiny, 1 block): chunk prefix per expert + l_aux.
// ---------------------------------------------------------------------------
__global__ __launch_bounds__(1024) void prefix_laux(int S, int nblk, int nchunks) {
    __shared__ float red[16][64];
    __shared__ float prod[64];
    const int tid = threadIdx.x;
    const int e = tid & 63, p = tid >> 6;   // p: 0..15

    float mp = 0.f;
    for (int b = p; b < nblk; b += 16) mp += g_me_partial[(size_t)b * 64 + e];
    red[p][e] = mp;

    if (tid < 64) {
        int run = 0;
        for (int c = 0; c < nchunks; ++c) {
            int t = g_cnt[c * 64 + tid];
            g_base[c * 64 + tid] = run;
            run += t;
        }
        prod[tid] = (float)run / (float)S;   // ce (pre-drop counts)
    }
    __syncthreads();
    if (tid < 64) {
        float me = 0.f;
#pragma unroll
        for (int q = 0; q < 16; ++q) me += red[q][tid];
        prod[tid] *= me / (float)S;
    }
    __syncthreads();
    if (tid == 0) {
        float sum = 0.f;
        for (int ee = 0; ee < 64; ++ee) sum += prod[ee];
        g_laux = sum * (float)NEXPERTS;      // mean(me*ce)*E^2 = sum*E
    }
}

// ---------------------------------------------------------------------------
// Kernel 4: sparse scatter into the (zeroed) output. Runs after the join.
// ---------------------------------------------------------------------------
__global__ void scatter_out(float* __restrict__ out, int S, int C,
                            long long comb_off, long long disp_off, int write_aux) {
    int s = blockIdx.x * blockDim.x + threadIdx.x;
    if (s == 0 && write_aux) out[0] = g_laux;
    if (s < S) {
        int e = g_idx[s];
        int r = g_base[(s >> 9) * 64 + e] + g_rank[s];
        if (r < C) {
            size_t pos = ((size_t)s * NEXPERTS + e) * (size_t)C + r;
            out[(size_t)comb_off + pos] = g_gate[s];
            if (disp_off >= 0)
                out[(size_t)disp_off + pos] = 1.0f;
        }
    }
}

extern "C" void kernel_launch(void* const* d_in, const int* in_sizes, int n_in,
                              void* d_out, int out_size) {
    const float* x  = (const float*)d_in[0];
    const float* wg = (const float*)d_in[1];
    const int D = in_sizes[1] / NEXPERTS;
    const int S = in_sizes[0] / D;
    const int C = (S + NEXPERTS - 1) / NEXPERTS;   // capacity_factor = 1.0
    const size_t SEC = (size_t)S * NEXPERTS * C;
    const size_t osz = (size_t)out_size;

    // output layout: [l_aux(1)][combine(SEC)][dispatch(SEC)] when sizes match
    long long comb = 0, disp = -1; int aux = 0;
    if (osz >= 2 * SEC + 1)      { aux = 1; comb = 1; disp = 1 + (long long)SEC; }
    else if (osz >= 2 * SEC)     { comb = 0; disp = (long long)SEC; }

    const size_t n4 = osz >> 2;

    // Fork: zero-fill KERNEL (SM-side, unlike the R4 memset node that fell on
    // a 2TB/s copy engine) runs concurrently with the compute chain, which
    // only touches scratch. Join before the sparse scatter into d_out.
    cudaStream_t s1; cudaStreamCreate(&s1);
    cudaEvent_t ef, ej;
    cudaEventCreateWithFlags(&ef, cudaEventDisableTiming);
    cudaEventCreateWithFlags(&ej, cudaEventDisableTiming);

    cudaEventRecord(ef, 0);

    // branch A (main stream): compute chain on scratch
    gemm_softmax<<<S / 64, 128>>>(x, wg, D, S);
    hist_rank<<<S / 512, 512>>>();
    prefix_laux<<<1, 1024>>>(S, S / 64, S / 512);

    // branch B (forked stream): zero-fill of d_out
    cudaStreamWaitEvent(s1, ef, 0);
    zero_fill<<<592, 256, 0, s1>>>((float4*)d_out, n4, (float*)d_out, osz);
    cudaEventRecord(ej, s1);

    cudaStreamWaitEvent(0, ej, 0);                           // join
    scatter_out<<<(S + 255) / 256, 256>>>((float*)d_out, S, C, comb, disp, aux);
    // s1/ef/ej intentionally not destroyed: kernel_launch runs only a handful
    // of times (correctness + capture); destroying capture-referenced objects
    // mid-capture is unsafe.
}